// round 6
// baseline (speedup 1.0000x reference)
#include <cuda_runtime.h>

// Dilated attention, fused over all 4 rates. B=4,H=16,T=8192,D=64.
// One block (256 thr, 8 warps) per (b,h,64-token window). Warp w owns rows
// 8w..8w+7. Lane (a=lane>>3, b=lane&7) computes 2x2 score tiles:
// rows {8w+2a, 8w+2a+1} x keys {k0+16*blk+2b, +1}.
// Smem layout: XOR-swizzled, ST=64: element (row,col) at
//   row*64 + ((cb ^ ((row>>1)&7))<<2) + (col&3),  cb = col>>2.
// Row pairs (2r,2r+1) share the swizzle -> +64 offsets stay valid.
//   r1: S=8,  seg=w,   active iff w%2==h%2,        k0=8w   (special path)
//   r2: S=16, j2=w>>1, active iff j2==h%4,         k0=16*j2, NB2=1
//   r3: S=32, j3=w>>2, active iff (2W+j3)%8==h%8,  k0=32*j3, NB2=1,2
//   r4: S=64, active iff W%16==h%16,               k0=0,     NB2=1..4

__device__ __forceinline__ float dot4(float4 a, float4 b) {
    return a.x * b.x + a.y * b.y + a.z * b.z + a.w * b.w;
}

__device__ __forceinline__ void cp16(unsigned int saddr, const float* g) {
    asm volatile("cp.async.cg.shared.global [%0], [%1], 16;\n"
                 :: "r"(saddr), "l"(g));
}

// Generic segment, NB2 blocks of 16 keys.
template <int NB2>
__device__ __forceinline__ void seg16(
    const float* __restrict__ qs, const float* __restrict__ ks,
    const float* __restrict__ vs, int w, int lane, int k0,
    float* acc0, float* acc1)
{
    const int a = lane >> 3, b = lane & 7;
    const int r0 = (w << 3) + (a << 1), r1 = r0 + 1;
    const int swzQ = (r0 >> 1) & 7;
    const float* q0p = qs + r0 * 64;          // q1 row = q0p + 64, same swizzle

    float s0[2 * NB2], s1[2 * NB2];
#pragma unroll
    for (int m = 0; m < 2 * NB2; m++) { s0[m] = 0.f; s1[m] = 0.f; }

#pragma unroll
    for (int dc = 0; dc < 16; dc++) {
        const int qoff = ((dc ^ swzQ) << 2);
        float4 q0 = *reinterpret_cast<const float4*>(q0p + qoff);
        float4 q1 = *reinterpret_cast<const float4*>(q0p + 64 + qoff);
#pragma unroll
        for (int blk = 0; blk < NB2; blk++) {
            const int krow = k0 + 2 * b + 16 * blk;
            const int swzK = (krow >> 1) & 7;
            const float* kp = ks + krow * 64 + ((dc ^ swzK) << 2);
            float4 ka = *reinterpret_cast<const float4*>(kp);
            float4 kb = *reinterpret_cast<const float4*>(kp + 64);
            s0[2 * blk]     += dot4(q0, ka);
            s0[2 * blk + 1] += dot4(q0, kb);
            s1[2 * blk]     += dot4(q1, ka);
            s1[2 * blk + 1] += dot4(q1, kb);
        }
    }

    // causal mask + scale + softmax
    float mx0 = -1e30f, mx1 = -1e30f;
#pragma unroll
    for (int m = 0; m < 2 * NB2; m++) {
        int key = k0 + (m >> 1) * 16 + 2 * b + (m & 1);
        s0[m] = (key <= r0) ? s0[m] * 0.125f : -1e30f;
        s1[m] = (key <= r1) ? s1[m] * 0.125f : -1e30f;
        mx0 = fmaxf(mx0, s0[m]);
        mx1 = fmaxf(mx1, s1[m]);
    }
    mx0 = fmaxf(mx0, __shfl_xor_sync(0xffffffffu, mx0, 1));
    mx0 = fmaxf(mx0, __shfl_xor_sync(0xffffffffu, mx0, 2));
    mx0 = fmaxf(mx0, __shfl_xor_sync(0xffffffffu, mx0, 4));
    mx1 = fmaxf(mx1, __shfl_xor_sync(0xffffffffu, mx1, 1));
    mx1 = fmaxf(mx1, __shfl_xor_sync(0xffffffffu, mx1, 2));
    mx1 = fmaxf(mx1, __shfl_xor_sync(0xffffffffu, mx1, 4));
    float sum0 = 0.f, sum1 = 0.f;
#pragma unroll
    for (int m = 0; m < 2 * NB2; m++) {
        s0[m] = __expf(s0[m] - mx0); sum0 += s0[m];
        s1[m] = __expf(s1[m] - mx1); sum1 += s1[m];
    }
    sum0 += __shfl_xor_sync(0xffffffffu, sum0, 1);
    sum0 += __shfl_xor_sync(0xffffffffu, sum0, 2);
    sum0 += __shfl_xor_sync(0xffffffffu, sum0, 4);
    sum1 += __shfl_xor_sync(0xffffffffu, sum1, 1);
    sum1 += __shfl_xor_sync(0xffffffffu, sum1, 2);
    sum1 += __shfl_xor_sync(0xffffffffu, sum1, 4);
    float inv0 = 1.f / sum0, inv1 = 1.f / sum1;
#pragma unroll
    for (int m = 0; m < 2 * NB2; m++) { s0[m] *= inv0; s1[m] *= inv1; }

    // PV: prob for key c lives in lane (a<<3)|((c&15)>>1), reg (c>>4)*2+(c&1)
#pragma unroll
    for (int c = 0; c < 16 * NB2; c++) {
        const int src = (a << 3) | ((c & 15) >> 1);
        const int rg  = ((c >> 4) << 1) | (c & 1);
        float p0 = __shfl_sync(0xffffffffu, s0[rg], src);
        float p1 = __shfl_sync(0xffffffffu, s1[rg], src);
        const int vrow = k0 + c;
        const int vswz = (vrow >> 1) & 7;
        const float* vr = vs + vrow * 64 + ((b ^ vswz) << 2);
        float4 va = *reinterpret_cast<const float4*>(vr);
        float4 vb = *reinterpret_cast<const float4*>(vr + 32);
        acc0[0] += p0 * va.x; acc0[1] += p0 * va.y;
        acc0[2] += p0 * va.z; acc0[3] += p0 * va.w;
        acc0[4] += p0 * vb.x; acc0[5] += p0 * vb.y;
        acc0[6] += p0 * vb.z; acc0[7] += p0 * vb.w;
        acc1[0] += p1 * va.x; acc1[1] += p1 * va.y;
        acc1[2] += p1 * va.z; acc1[3] += p1 * va.w;
        acc1[4] += p1 * vb.x; acc1[5] += p1 * vb.y;
        acc1[6] += p1 * vb.z; acc1[7] += p1 * vb.w;
    }
}

// Rate-1 special path: S=8, keys = warp's own 8 rows. d-loop split across
// lane halves (bh = b>>2), combined via shfl_xor(...,4).
__device__ __forceinline__ void seg_r1(
    const float* __restrict__ qs, const float* __restrict__ ks,
    const float* __restrict__ vs, int w, int lane,
    float* acc0, float* acc1)
{
    const int a = lane >> 3, b = lane & 7, bp = b & 3, bh = b >> 2;
    const int r0 = (w << 3) + (a << 1), r1 = r0 + 1;
    const int k0 = w << 3;
    const int swzQ = (r0 >> 1) & 7;
    const int krow = k0 + 2 * bp;
    const int swzK = (krow >> 1) & 7;
    const float* q0p = qs + r0 * 64;
    const float* kpp = ks + krow * 64;

    float s00 = 0.f, s01 = 0.f, s10 = 0.f, s11 = 0.f;
#pragma unroll
    for (int t = 0; t < 8; t++) {
        const int cb = bh * 8 + t;
        const int qoff = ((cb ^ swzQ) << 2);
        const int koff = ((cb ^ swzK) << 2);
        float4 q0 = *reinterpret_cast<const float4*>(q0p + qoff);
        float4 q1 = *reinterpret_cast<const float4*>(q0p + 64 + qoff);
        float4 ka = *reinterpret_cast<const float4*>(kpp + koff);
        float4 kb = *reinterpret_cast<const float4*>(kpp + 64 + koff);
        s00 += dot4(q0, ka); s01 += dot4(q0, kb);
        s10 += dot4(q1, ka); s11 += dot4(q1, kb);
    }
    s00 += __shfl_xor_sync(0xffffffffu, s00, 4);
    s01 += __shfl_xor_sync(0xffffffffu, s01, 4);
    s10 += __shfl_xor_sync(0xffffffffu, s10, 4);
    s11 += __shfl_xor_sync(0xffffffffu, s11, 4);

    const int key0 = k0 + 2 * bp, key1 = key0 + 1;
    s00 = (key0 <= r0) ? s00 * 0.125f : -1e30f;
    s01 = (key1 <= r0) ? s01 * 0.125f : -1e30f;
    s10 = (key0 <= r1) ? s10 * 0.125f : -1e30f;
    s11 = (key1 <= r1) ? s11 * 0.125f : -1e30f;

    float mx0 = fmaxf(s00, s01), mx1 = fmaxf(s10, s11);
    mx0 = fmaxf(mx0, __shfl_xor_sync(0xffffffffu, mx0, 1));
    mx0 = fmaxf(mx0, __shfl_xor_sync(0xffffffffu, mx0, 2));
    mx1 = fmaxf(mx1, __shfl_xor_sync(0xffffffffu, mx1, 1));
    mx1 = fmaxf(mx1, __shfl_xor_sync(0xffffffffu, mx1, 2));
    s00 = __expf(s00 - mx0); s01 = __expf(s01 - mx0);
    s10 = __expf(s10 - mx1); s11 = __expf(s11 - mx1);
    float sum0 = s00 + s01, sum1 = s10 + s11;
    sum0 += __shfl_xor_sync(0xffffffffu, sum0, 1);
    sum0 += __shfl_xor_sync(0xffffffffu, sum0, 2);
    sum1 += __shfl_xor_sync(0xffffffffu, sum1, 1);
    sum1 += __shfl_xor_sync(0xffffffffu, sum1, 2);
    float inv0 = 1.f / sum0, inv1 = 1.f / sum1;
    s00 *= inv0; s01 *= inv0; s10 *= inv1; s11 *= inv1;

#pragma unroll
    for (int c = 0; c < 8; c++) {
        const int src = (a << 3) | (c >> 1);
        float p0 = __shfl_sync(0xffffffffu, (c & 1) ? s01 : s00, src);
        float p1 = __shfl_sync(0xffffffffu, (c & 1) ? s11 : s10, src);
        const int vrow = k0 + c;
        const int vswz = (vrow >> 1) & 7;
        const float* vr = vs + vrow * 64 + ((b ^ vswz) << 2);
        float4 va = *reinterpret_cast<const float4*>(vr);
        float4 vb = *reinterpret_cast<const float4*>(vr + 32);
        acc0[0] += p0 * va.x; acc0[1] += p0 * va.y;
        acc0[2] += p0 * va.z; acc0[3] += p0 * va.w;
        acc0[4] += p0 * vb.x; acc0[5] += p0 * vb.y;
        acc0[6] += p0 * vb.z; acc0[7] += p0 * vb.w;
        acc1[0] += p1 * va.x; acc1[1] += p1 * va.y;
        acc1[2] += p1 * va.z; acc1[3] += p1 * va.w;
        acc1[4] += p1 * vb.x; acc1[5] += p1 * vb.y;
        acc1[6] += p1 * vb.z; acc1[7] += p1 * vb.w;
    }
}

#define SMEM_KS (64 * 64)
#define SMEM_VS (2 * 64 * 64)
#define SMEM_FLOATS (3 * 64 * 64)
#define SMEM_BYTES  (SMEM_FLOATS * 4)

__global__ void __launch_bounds__(256, 4)
dilated_attn_kernel(const float* __restrict__ Q, const float* __restrict__ K,
                    const float* __restrict__ V, float* __restrict__ out)
{
    extern __shared__ float smem[];
    float* qs = smem;
    float* ks = smem + SMEM_KS;
    float* vs = smem + SMEM_VS;

    const int wWin = blockIdx.x;
    const int h    = blockIdx.y;
    const int b_   = blockIdx.z;
    const int tid  = threadIdx.x;
    const int base = ((b_ * 16 + h) * 8192 + wWin * 64) * 64;

    const bool r4_act = ((wWin & 15) == (h & 15));

    // cooperative tile load (cp.async.cg, L1-bypass), swizzled store offsets
    {
        unsigned int qa = (unsigned int)__cvta_generic_to_shared(qs);
        unsigned int ka = (unsigned int)__cvta_generic_to_shared(ks);
        unsigned int va = (unsigned int)__cvta_generic_to_shared(vs);
#pragma unroll
        for (int it = 0; it < 4; it++) {
            int idx = tid + it * 256;          // 0..1023 float4s
            int row = idx >> 4;
            int cb  = idx & 15;
            bool need = (((row >> 3) & 1) == (h & 1))
                     || ((row >> 4) == (h & 3))
                     || ((((wWin << 1) + (row >> 5)) & 7) == (h & 7))
                     || r4_act;
            if (need) {
                int swz = (row >> 1) & 7;
                unsigned int so = (unsigned int)(row * 64 + ((cb ^ swz) << 2)) * 4u;
                int go = base + row * 64 + cb * 4;
                cp16(qa + so, Q + go);
                cp16(ka + so, K + go);
                cp16(va + so, V + go);
            }
        }
        asm volatile("cp.async.commit_group;\n");
        asm volatile("cp.async.wait_group 0;\n");
    }
    __syncthreads();

    const int w    = tid >> 5;   // 0..7
    const int lane = tid & 31;

    float acc0[8], acc1[8];
#pragma unroll
    for (int j = 0; j < 8; j++) { acc0[j] = 0.f; acc1[j] = 0.f; }

    // rate 1 (S=8)
    if ((w & 1) == (h & 1))
        seg_r1(qs, ks, vs, w, lane, acc0, acc1);

    // rate 2 (S=16): seg j2 = w>>1
    if ((w >> 1) == (h & 3))
        seg16<1>(qs, ks, vs, w, lane, (w >> 1) << 4, acc0, acc1);

    // rate 3 (S=32): seg j3 = w>>2
    {
        int j3 = w >> 2;
        if ((((wWin << 1) + j3) & 7) == (h & 7)) {
            int k0 = j3 << 5;
            if ((w & 3) < 2) seg16<1>(qs, ks, vs, w, lane, k0, acc0, acc1);
            else             seg16<2>(qs, ks, vs, w, lane, k0, acc0, acc1);
        }
    }

    // rate 4 (S=64)
    if (r4_act) {
        switch (w >> 1) {
            case 0: seg16<1>(qs, ks, vs, w, lane, 0, acc0, acc1); break;
            case 1: seg16<2>(qs, ks, vs, w, lane, 0, acc0, acc1); break;
            case 2: seg16<3>(qs, ks, vs, w, lane, 0, acc0, acc1); break;
            case 3: seg16<4>(qs, ks, vs, w, lane, 0, acc0, acc1); break;
        }
    }

    // write (avg over 4 rates); untouched rows emit zeros
    const int a = lane >> 3, bb = lane & 7;
    const int r0 = (w << 3) + (a << 1);
    float* o0 = out + base + r0 * 64 + 4 * bb;
    float* o1 = o0 + 64;
    float4 t;
    t.x = acc0[0] * 0.25f; t.y = acc0[1] * 0.25f;
    t.z = acc0[2] * 0.25f; t.w = acc0[3] * 0.25f;
    *reinterpret_cast<float4*>(o0) = t;
    t.x = acc0[4] * 0.25f; t.y = acc0[5] * 0.25f;
    t.z = acc0[6] * 0.25f; t.w = acc0[7] * 0.25f;
    *reinterpret_cast<float4*>(o0 + 32) = t;
    t.x = acc1[0] * 0.25f; t.y = acc1[1] * 0.25f;
    t.z = acc1[2] * 0.25f; t.w = acc1[3] * 0.25f;
    *reinterpret_cast<float4*>(o1) = t;
    t.x = acc1[4] * 0.25f; t.y = acc1[5] * 0.25f;
    t.z = acc1[6] * 0.25f; t.w = acc1[7] * 0.25f;
    *reinterpret_cast<float4*>(o1 + 32) = t;
}

extern "C" void kernel_launch(void* const* d_in, const int* in_sizes, int n_in,
                              void* d_out, int out_size)
{
    const float* Q = (const float*)d_in[0];
    const float* K = (const float*)d_in[1];
    const float* V = (const float*)d_in[2];
    float* out = (float*)d_out;

    cudaFuncSetAttribute(dilated_attn_kernel,
                         cudaFuncAttributeMaxDynamicSharedMemorySize, SMEM_BYTES);

    dim3 grid(128, 16, 4);
    dilated_attn_kernel<<<grid, 256, SMEM_BYTES>>>(Q, K, V, out);
}

// round 7
// speedup vs baseline: 1.0417x; 1.0417x over previous
#include <cuda_runtime.h>

// Dilated attention, fused over all 4 rates. B=4,H=16,T=8192,D=64.
// One block (256 thr, 8 warps) per (b,h,64-token window). Warp w owns rows
// 8w..8w+7. Lane (a=lane>>3, b=lane&7) computes 2x2 score tiles:
// rows {8w+2a, 8w+2a+1} x keys {k0+16*blk+2b, +1}.
// Smem: XOR-swizzled, ST=64: element (row,col) at
//   row*64 + ((cb ^ ((row>>1)&7))<<2) + (col&3),  cb = col>>2.
// Row pairs (2r,2r+1) share the swizzle -> +64 offsets stay valid.
//   r1: S=8,  seg=w,   active iff w%2==h%2,        k0=8w   (special path)
//   r2: S=16, j2=w>>1, active iff j2==h%4,         k0=16*j2, NB2=1
//   r3: S=32, j3=w>>2, active iff (2W+j3)%8==h%8,  k0=32*j3, NB2=1,2
//   r4: S=64, active iff W%16==h%16,               k0=0,     NB2=1..4

__device__ __forceinline__ float dot4(float4 a, float4 b) {
    return a.x * b.x + a.y * b.y + a.z * b.z + a.w * b.w;
}

__device__ __forceinline__ void cp16(unsigned int saddr, const float* g) {
    asm volatile("cp.async.cg.shared.global [%0], [%1], 16;\n"
                 :: "r"(saddr), "l"(g));
}

// Generic segment, NB2 blocks of 16 keys.
template <int NB2>
__device__ __forceinline__ void seg16(
    const float* __restrict__ qs, const float* __restrict__ ks,
    const float* __restrict__ vs, int w, int lane, int k0,
    float* acc0, float* acc1)
{
    const int a = lane >> 3, b = lane & 7;
    const int r0 = (w << 3) + (a << 1), r1 = r0 + 1;
    const int swzQ = (r0 >> 1) & 7;
    const float* q0p = qs + r0 * 64;          // q1 row = q0p + 64, same swizzle

    float s0[2 * NB2], s1[2 * NB2];
#pragma unroll
    for (int m = 0; m < 2 * NB2; m++) { s0[m] = 0.f; s1[m] = 0.f; }

#pragma unroll
    for (int dc = 0; dc < 16; dc++) {
        const int qoff = ((dc ^ swzQ) << 2);
        float4 q0 = *reinterpret_cast<const float4*>(q0p + qoff);
        float4 q1 = *reinterpret_cast<const float4*>(q0p + 64 + qoff);
#pragma unroll
        for (int blk = 0; blk < NB2; blk++) {
            const int krow = k0 + 2 * b + 16 * blk;
            const int swzK = (krow >> 1) & 7;
            const float* kp = ks + krow * 64 + ((dc ^ swzK) << 2);
            float4 ka = *reinterpret_cast<const float4*>(kp);
            float4 kb = *reinterpret_cast<const float4*>(kp + 64);
            s0[2 * blk]     += dot4(q0, ka);
            s0[2 * blk + 1] += dot4(q0, kb);
            s1[2 * blk]     += dot4(q1, ka);
            s1[2 * blk + 1] += dot4(q1, kb);
        }
    }

    // causal mask + scale + softmax
    float mx0 = -1e30f, mx1 = -1e30f;
#pragma unroll
    for (int m = 0; m < 2 * NB2; m++) {
        int key = k0 + (m >> 1) * 16 + 2 * b + (m & 1);
        s0[m] = (key <= r0) ? s0[m] * 0.125f : -1e30f;
        s1[m] = (key <= r1) ? s1[m] * 0.125f : -1e30f;
        mx0 = fmaxf(mx0, s0[m]);
        mx1 = fmaxf(mx1, s1[m]);
    }
    mx0 = fmaxf(mx0, __shfl_xor_sync(0xffffffffu, mx0, 1));
    mx0 = fmaxf(mx0, __shfl_xor_sync(0xffffffffu, mx0, 2));
    mx0 = fmaxf(mx0, __shfl_xor_sync(0xffffffffu, mx0, 4));
    mx1 = fmaxf(mx1, __shfl_xor_sync(0xffffffffu, mx1, 1));
    mx1 = fmaxf(mx1, __shfl_xor_sync(0xffffffffu, mx1, 2));
    mx1 = fmaxf(mx1, __shfl_xor_sync(0xffffffffu, mx1, 4));
    float sum0 = 0.f, sum1 = 0.f;
#pragma unroll
    for (int m = 0; m < 2 * NB2; m++) {
        s0[m] = __expf(s0[m] - mx0); sum0 += s0[m];
        s1[m] = __expf(s1[m] - mx1); sum1 += s1[m];
    }
    sum0 += __shfl_xor_sync(0xffffffffu, sum0, 1);
    sum0 += __shfl_xor_sync(0xffffffffu, sum0, 2);
    sum0 += __shfl_xor_sync(0xffffffffu, sum0, 4);
    sum1 += __shfl_xor_sync(0xffffffffu, sum1, 1);
    sum1 += __shfl_xor_sync(0xffffffffu, sum1, 2);
    sum1 += __shfl_xor_sync(0xffffffffu, sum1, 4);
    float inv0 = 1.f / sum0, inv1 = 1.f / sum1;
#pragma unroll
    for (int m = 0; m < 2 * NB2; m++) { s0[m] *= inv0; s1[m] *= inv1; }

    // PV: prob for key c lives in lane (a<<3)|((c&15)>>1), reg (c>>4)*2+(c&1).
    // V loads issue first so LDS latency overlaps the shfl latency.
#pragma unroll
    for (int c = 0; c < 16 * NB2; c++) {
        const int vrow = k0 + c;
        const int vswz = (vrow >> 1) & 7;
        const float* vr = vs + vrow * 64 + ((b ^ vswz) << 2);
        float4 va = *reinterpret_cast<const float4*>(vr);
        float4 vb = *reinterpret_cast<const float4*>(vr + 32);
        const int src = (a << 3) | ((c & 15) >> 1);
        const int rg  = ((c >> 4) << 1) | (c & 1);
        float p0 = __shfl_sync(0xffffffffu, s0[rg], src);
        float p1 = __shfl_sync(0xffffffffu, s1[rg], src);
        acc0[0] += p0 * va.x; acc0[1] += p0 * va.y;
        acc0[2] += p0 * va.z; acc0[3] += p0 * va.w;
        acc0[4] += p0 * vb.x; acc0[5] += p0 * vb.y;
        acc0[6] += p0 * vb.z; acc0[7] += p0 * vb.w;
        acc1[0] += p1 * va.x; acc1[1] += p1 * va.y;
        acc1[2] += p1 * va.z; acc1[3] += p1 * va.w;
        acc1[4] += p1 * vb.x; acc1[5] += p1 * vb.y;
        acc1[6] += p1 * vb.z; acc1[7] += p1 * vb.w;
    }
}

// Rate-1 special path: S=8, keys = warp's own 8 rows. d-loop split across
// lane halves (bh = b>>2), combined via shfl_xor(...,4).
__device__ __forceinline__ void seg_r1(
    const float* __restrict__ qs, const float* __restrict__ ks,
    const float* __restrict__ vs, int w, int lane,
    float* acc0, float* acc1)
{
    const int a = lane >> 3, b = lane & 7, bp = b & 3, bh = b >> 2;
    const int r0 = (w << 3) + (a << 1), r1 = r0 + 1;
    const int k0 = w << 3;
    const int swzQ = (r0 >> 1) & 7;
    const int krow = k0 + 2 * bp;
    const int swzK = (krow >> 1) & 7;
    const float* q0p = qs + r0 * 64;
    const float* kpp = ks + krow * 64;

    float s00 = 0.f, s01 = 0.f, s10 = 0.f, s11 = 0.f;
#pragma unroll
    for (int t = 0; t < 8; t++) {
        const int cb = bh * 8 + t;
        const int qoff = ((cb ^ swzQ) << 2);
        const int koff = ((cb ^ swzK) << 2);
        float4 q0 = *reinterpret_cast<const float4*>(q0p + qoff);
        float4 q1 = *reinterpret_cast<const float4*>(q0p + 64 + qoff);
        float4 ka = *reinterpret_cast<const float4*>(kpp + koff);
        float4 kb = *reinterpret_cast<const float4*>(kpp + 64 + koff);
        s00 += dot4(q0, ka); s01 += dot4(q0, kb);
        s10 += dot4(q1, ka); s11 += dot4(q1, kb);
    }
    s00 += __shfl_xor_sync(0xffffffffu, s00, 4);
    s01 += __shfl_xor_sync(0xffffffffu, s01, 4);
    s10 += __shfl_xor_sync(0xffffffffu, s10, 4);
    s11 += __shfl_xor_sync(0xffffffffu, s11, 4);

    const int key0 = k0 + 2 * bp, key1 = key0 + 1;
    s00 = (key0 <= r0) ? s00 * 0.125f : -1e30f;
    s01 = (key1 <= r0) ? s01 * 0.125f : -1e30f;
    s10 = (key0 <= r1) ? s10 * 0.125f : -1e30f;
    s11 = (key1 <= r1) ? s11 * 0.125f : -1e30f;

    float mx0 = fmaxf(s00, s01), mx1 = fmaxf(s10, s11);
    mx0 = fmaxf(mx0, __shfl_xor_sync(0xffffffffu, mx0, 1));
    mx0 = fmaxf(mx0, __shfl_xor_sync(0xffffffffu, mx0, 2));
    mx1 = fmaxf(mx1, __shfl_xor_sync(0xffffffffu, mx1, 1));
    mx1 = fmaxf(mx1, __shfl_xor_sync(0xffffffffu, mx1, 2));
    s00 = __expf(s00 - mx0); s01 = __expf(s01 - mx0);
    s10 = __expf(s10 - mx1); s11 = __expf(s11 - mx1);
    float sum0 = s00 + s01, sum1 = s10 + s11;
    sum0 += __shfl_xor_sync(0xffffffffu, sum0, 1);
    sum0 += __shfl_xor_sync(0xffffffffu, sum0, 2);
    sum1 += __shfl_xor_sync(0xffffffffu, sum1, 1);
    sum1 += __shfl_xor_sync(0xffffffffu, sum1, 2);
    float inv0 = 1.f / sum0, inv1 = 1.f / sum1;
    s00 *= inv0; s01 *= inv0; s10 *= inv1; s11 *= inv1;

#pragma unroll
    for (int c = 0; c < 8; c++) {
        const int vrow = k0 + c;
        const int vswz = (vrow >> 1) & 7;
        const float* vr = vs + vrow * 64 + ((b ^ vswz) << 2);
        float4 va = *reinterpret_cast<const float4*>(vr);
        float4 vb = *reinterpret_cast<const float4*>(vr + 32);
        const int src = (a << 3) | (c >> 1);
        float p0 = __shfl_sync(0xffffffffu, (c & 1) ? s01 : s00, src);
        float p1 = __shfl_sync(0xffffffffu, (c & 1) ? s11 : s10, src);
        acc0[0] += p0 * va.x; acc0[1] += p0 * va.y;
        acc0[2] += p0 * va.z; acc0[3] += p0 * va.w;
        acc0[4] += p0 * vb.x; acc0[5] += p0 * vb.y;
        acc0[6] += p0 * vb.z; acc0[7] += p0 * vb.w;
        acc1[0] += p1 * va.x; acc1[1] += p1 * va.y;
        acc1[2] += p1 * va.z; acc1[3] += p1 * va.w;
        acc1[4] += p1 * vb.x; acc1[5] += p1 * vb.y;
        acc1[6] += p1 * vb.z; acc1[7] += p1 * vb.w;
    }
}

#define SMEM_KS (64 * 64)
#define SMEM_VS (2 * 64 * 64)
#define SMEM_FLOATS (3 * 64 * 64)
#define SMEM_BYTES  (SMEM_FLOATS * 4)

__global__ void __launch_bounds__(256, 3)
dilated_attn_kernel(const float* __restrict__ Q, const float* __restrict__ K,
                    const float* __restrict__ V, float* __restrict__ out)
{
    extern __shared__ float smem[];
    float* qs = smem;
    float* ks = smem + SMEM_KS;
    float* vs = smem + SMEM_VS;

    const int wWin = blockIdx.x;
    const int h    = blockIdx.y;
    const int b_   = blockIdx.z;
    const int tid  = threadIdx.x;
    const int base = ((b_ * 16 + h) * 8192 + wWin * 64) * 64;

    const bool r4_act = ((wWin & 15) == (h & 15));

    // cooperative tile load (cp.async.cg, L1-bypass), swizzled store offsets
    {
        unsigned int qa = (unsigned int)__cvta_generic_to_shared(qs);
        unsigned int ka = (unsigned int)__cvta_generic_to_shared(ks);
        unsigned int va = (unsigned int)__cvta_generic_to_shared(vs);
#pragma unroll
        for (int it = 0; it < 4; it++) {
            int idx = tid + it * 256;          // 0..1023 float4s
            int row = idx >> 4;
            int cb  = idx & 15;
            bool need = (((row >> 3) & 1) == (h & 1))
                     || ((row >> 4) == (h & 3))
                     || ((((wWin << 1) + (row >> 5)) & 7) == (h & 7))
                     || r4_act;
            if (need) {
                int swz = (row >> 1) & 7;
                unsigned int so = (unsigned int)(row * 64 + ((cb ^ swz) << 2)) * 4u;
                int go = base + row * 64 + cb * 4;
                cp16(qa + so, Q + go);
                cp16(ka + so, K + go);
                cp16(va + so, V + go);
            }
        }
        asm volatile("cp.async.commit_group;\n");
        asm volatile("cp.async.wait_group 0;\n");
    }
    __syncthreads();

    const int w    = tid >> 5;   // 0..7
    const int lane = tid & 31;

    float acc0[8], acc1[8];
#pragma unroll
    for (int j = 0; j < 8; j++) { acc0[j] = 0.f; acc1[j] = 0.f; }

    // rate 1 (S=8)
    if ((w & 1) == (h & 1))
        seg_r1(qs, ks, vs, w, lane, acc0, acc1);

    // rate 2 (S=16): seg j2 = w>>1
    if ((w >> 1) == (h & 3))
        seg16<1>(qs, ks, vs, w, lane, (w >> 1) << 4, acc0, acc1);

    // rate 3 (S=32): seg j3 = w>>2
    {
        int j3 = w >> 2;
        if ((((wWin << 1) + j3) & 7) == (h & 7)) {
            int k0 = j3 << 5;
            if ((w & 3) < 2) seg16<1>(qs, ks, vs, w, lane, k0, acc0, acc1);
            else             seg16<2>(qs, ks, vs, w, lane, k0, acc0, acc1);
        }
    }

    // rate 4 (S=64)
    if (r4_act) {
        switch (w >> 1) {
            case 0: seg16<1>(qs, ks, vs, w, lane, 0, acc0, acc1); break;
            case 1: seg16<2>(qs, ks, vs, w, lane, 0, acc0, acc1); break;
            case 2: seg16<3>(qs, ks, vs, w, lane, 0, acc0, acc1); break;
            case 3: seg16<4>(qs, ks, vs, w, lane, 0, acc0, acc1); break;
        }
    }

    // write (avg over 4 rates); untouched rows emit zeros
    const int a = lane >> 3, bb = lane & 7;
    const int r0 = (w << 3) + (a << 1);
    float* o0 = out + base + r0 * 64 + 4 * bb;
    float* o1 = o0 + 64;
    float4 t;
    t.x = acc0[0] * 0.25f; t.y = acc0[1] * 0.25f;
    t.z = acc0[2] * 0.25f; t.w = acc0[3] * 0.25f;
    *reinterpret_cast<float4*>(o0) = t;
    t.x = acc0[4] * 0.25f; t.y = acc0[5] * 0.25f;
    t.z = acc0[6] * 0.25f; t.w = acc0[7] * 0.25f;
    *reinterpret_cast<float4*>(o0 + 32) = t;
    t.x = acc1[0] * 0.25f; t.y = acc1[1] * 0.25f;
    t.z = acc1[2] * 0.25f; t.w = acc1[3] * 0.25f;
    *reinterpret_cast<float4*>(o1) = t;
    t.x = acc1[4] * 0.25f; t.y = acc1[5] * 0.25f;
    t.z = acc1[6] * 0.25f; t.w = acc1[7] * 0.25f;
    *reinterpret_cast<float4*>(o1 + 32) = t;
}

extern "C" void kernel_launch(void* const* d_in, const int* in_sizes, int n_in,
                              void* d_out, int out_size)
{
    const float* Q = (const float*)d_in[0];
    const float* K = (const float*)d_in[1];
    const float* V = (const float*)d_in[2];
    float* out = (float*)d_out;

    cudaFuncSetAttribute(dilated_attn_kernel,
                         cudaFuncAttributeMaxDynamicSharedMemorySize, SMEM_BYTES);

    dim3 grid(128, 16, 4);
    dilated_attn_kernel<<<grid, 256, SMEM_BYTES>>>(Q, K, V, out);
}

// round 8
// speedup vs baseline: 2.7959x; 2.6839x over previous
#include <cuda_runtime.h>

// Dilated attention, fused over all 4 rates with nested-suffix rate fusion.
// B=4,H=16,T=8192,D=64. One block (512 thr, 16 warps) per (b,h,64-token
// window). Warp t owns rows 4t..4t+3. Lane: i=lane>>3 (row), kk=lane&7
// (key slot / d-eighth). Keys for lane: k0+8m+kk.
// Per warp, all active rates' key ranges are nested suffixes of the largest
// active rate's range -> compute scores once over the union, per-rate masked
// softmax from the same registers, combined weights, single PV pass.
//   r1: S=8,  j1=t>>1, active iff j1%2==h%2,         k0=8*j1
//   r2: S=16, j2=t>>2, active iff j2==h%4,           k0=16*j2
//   r3: S=32, j3=t>>3, active iff (2W+j3)%8==h%8,    k0=32*j3
//   r4: S=64, active iff W%16==h%16,                 k0=0

#define STRIDE 68   // smem row stride (floats), conflict-free, 16B-aligned

__device__ __forceinline__ float dot4(float4 a, float4 b) {
    return a.x * b.x + a.y * b.y + a.z * b.z + a.w * b.w;
}

__device__ __forceinline__ void cp16(unsigned int saddr, const float* g) {
    asm volatile("cp.async.cg.shared.global [%0], [%1], 16;\n"
                 :: "r"(saddr), "l"(g));
}

// One masked softmax pass for a sub-rate whose range starts at kr (suffix of
// the union range). Adds its normalized probs into wsum.
template <int NBP>
__device__ __forceinline__ void sub_rate(
    const float* sc, float* wsum, int k0, int kk, int kr)
{
    float t[NBP];
    float mx = -1e30f;
#pragma unroll
    for (int m = 0; m < NBP; m++) {
        int key = k0 + 8 * m + kk;
        t[m] = (key >= kr) ? sc[m] : -1e30f;
        mx = fmaxf(mx, t[m]);
    }
    mx = fmaxf(mx, __shfl_xor_sync(0xffffffffu, mx, 1));
    mx = fmaxf(mx, __shfl_xor_sync(0xffffffffu, mx, 2));
    mx = fmaxf(mx, __shfl_xor_sync(0xffffffffu, mx, 4));
    float sum = 0.f;
#pragma unroll
    for (int m = 0; m < NBP; m++) {
        float e = __expf(t[m] - mx);
        sum += e;
        t[m] = e;
    }
    sum += __shfl_xor_sync(0xffffffffu, sum, 1);
    sum += __shfl_xor_sync(0xffffffffu, sum, 2);
    sum += __shfl_xor_sync(0xffffffffu, sum, 4);
    float inv = 1.f / sum;
#pragma unroll
    for (int m = 0; m < NBP; m++) wsum[m] += t[m] * inv;
}

// Union segment over NBP key-blocks of 8; union rate softmax + up to 3
// nested sub-rates; one PV pass with combined weights.
template <int NBP>
__device__ __forceinline__ void seg_multi(
    const float* __restrict__ qs, const float* __restrict__ ks,
    const float* __restrict__ vs, int w_id, int lane, int k0,
    int kA, bool aA, int kB, bool aB, int kC, bool aC, float* acc)
{
    const int i  = lane >> 3;
    const int kk = lane & 7;
    const int qr = (w_id << 2) + i;
    const float* qrow  = qs + qr * STRIDE;
    const float* kbase = ks + (k0 + kk) * STRIDE;

    // scores over the union range
    float sc[NBP];
#pragma unroll
    for (int m = 0; m < NBP; m++) sc[m] = 0.f;
#pragma unroll 4
    for (int dc = 0; dc < 16; dc++) {
        float4 qv = *reinterpret_cast<const float4*>(qrow + dc * 4);
#pragma unroll
        for (int m = 0; m < NBP; m++) {
            float4 kv = *reinterpret_cast<const float4*>(kbase + m * 8 * STRIDE + dc * 4);
            sc[m] += dot4(qv, kv);
        }
    }

    // causal mask + scale
#pragma unroll
    for (int m = 0; m < NBP; m++) {
        int key = k0 + 8 * m + kk;
        sc[m] = (key <= qr) ? sc[m] * 0.125f : -1e30f;
    }

    // union-rate softmax -> wsum
    float wsum[NBP];
    {
        float mx = -1e30f;
#pragma unroll
        for (int m = 0; m < NBP; m++) mx = fmaxf(mx, sc[m]);
        mx = fmaxf(mx, __shfl_xor_sync(0xffffffffu, mx, 1));
        mx = fmaxf(mx, __shfl_xor_sync(0xffffffffu, mx, 2));
        mx = fmaxf(mx, __shfl_xor_sync(0xffffffffu, mx, 4));
        float sum = 0.f;
#pragma unroll
        for (int m = 0; m < NBP; m++) {
            float e = __expf(sc[m] - mx);
            sum += e;
            wsum[m] = e;
        }
        sum += __shfl_xor_sync(0xffffffffu, sum, 1);
        sum += __shfl_xor_sync(0xffffffffu, sum, 2);
        sum += __shfl_xor_sync(0xffffffffu, sum, 4);
        float inv = 1.f / sum;
#pragma unroll
        for (int m = 0; m < NBP; m++) wsum[m] *= inv;
    }

    // nested sub-rates (warp-uniform branches)
    if (aA) sub_rate<NBP>(sc, wsum, k0, kk, kA);
    if (aB) sub_rate<NBP>(sc, wsum, k0, kk, kB);
    if (aC) sub_rate<NBP>(sc, wsum, k0, kk, kC);

    // PV: lane accumulates its d-eighth of its row over all union keys
    const int srcbase = lane & ~7;
    const float* vbase = vs + k0 * STRIDE + kk * 8;
#pragma unroll 4
    for (int c = 0; c < NBP * 8; c++) {
        float p = __shfl_sync(0xffffffffu, wsum[c >> 3], srcbase | (c & 7));
        const float* vr = vbase + c * STRIDE;
        float4 v0 = *reinterpret_cast<const float4*>(vr);
        float4 v1 = *reinterpret_cast<const float4*>(vr + 4);
        acc[0] += p * v0.x; acc[1] += p * v0.y;
        acc[2] += p * v0.z; acc[3] += p * v0.w;
        acc[4] += p * v1.x; acc[5] += p * v1.y;
        acc[6] += p * v1.z; acc[7] += p * v1.w;
    }
}

#define SMEM_KS (64 * STRIDE)
#define SMEM_VS (2 * 64 * STRIDE)
#define SMEM_FLOATS (3 * 64 * STRIDE)
#define SMEM_BYTES  (SMEM_FLOATS * 4)

__global__ void __launch_bounds__(512, 3)
dilated_attn_kernel(const float* __restrict__ Q, const float* __restrict__ K,
                    const float* __restrict__ V, float* __restrict__ out)
{
    extern __shared__ float smem[];
    float* qs = smem;
    float* ks = smem + SMEM_KS;
    float* vs = smem + SMEM_VS;

    const int wWin = blockIdx.x;
    const int h    = blockIdx.y;
    const int b    = blockIdx.z;
    const int tid  = threadIdx.x;
    const int base = ((b * 16 + h) * 8192 + wWin * 64) * 64;

    const bool r4_act = ((wWin & 15) == (h & 15));

    // cooperative tile load via cp.async.cg, skipping never-touched rows
    {
        unsigned int qa = (unsigned int)__cvta_generic_to_shared(qs);
        unsigned int ka = (unsigned int)__cvta_generic_to_shared(ks);
        unsigned int va = (unsigned int)__cvta_generic_to_shared(vs);
#pragma unroll
        for (int it = 0; it < 2; it++) {
            int idx = tid + it * 512;          // 0..1023 float4s
            int row = idx >> 4;
            int col = (idx & 15) << 2;
            bool need = (((row >> 3) & 1) == (h & 1))
                     || ((row >> 4) == (h & 3))
                     || ((((wWin << 1) + (row >> 5)) & 7) == (h & 7))
                     || r4_act;
            if (need) {
                unsigned int so = (unsigned int)(row * STRIDE + col) * 4u;
                int go = base + row * 64 + col;
                cp16(qa + so, Q + go);
                cp16(ka + so, K + go);
                cp16(va + so, V + go);
            }
        }
        asm volatile("cp.async.commit_group;\n");
        asm volatile("cp.async.wait_group 0;\n");
    }
    __syncthreads();

    const int w_id = tid >> 5;   // 0..15
    const int lane = tid & 31;

    float acc[8];
#pragma unroll
    for (int j = 0; j < 8; j++) acc[j] = 0.f;

    // rate activity (warp-uniform)
    const int j1 = w_id >> 1, j2 = w_id >> 2, j3 = w_id >> 3;
    const bool A1 = (j1 & 1) == (h & 1);
    const bool A2 = j2 == (h & 3);
    const bool A3 = ((((wWin << 1) + j3) & 7) == (h & 7));
    const int k1 = j1 << 3, k2 = j2 << 4, k3 = j3 << 5;

    if (r4_act) {
        // union = r4 (whole window); subs = any of r3,r2,r1
        switch (w_id >> 1) {
            case 0: seg_multi<1>(qs, ks, vs, w_id, lane, 0, k3, A3, k2, A2, k1, A1, acc); break;
            case 1: seg_multi<2>(qs, ks, vs, w_id, lane, 0, k3, A3, k2, A2, k1, A1, acc); break;
            case 2: seg_multi<3>(qs, ks, vs, w_id, lane, 0, k3, A3, k2, A2, k1, A1, acc); break;
            case 3: seg_multi<4>(qs, ks, vs, w_id, lane, 0, k3, A3, k2, A2, k1, A1, acc); break;
            case 4: seg_multi<5>(qs, ks, vs, w_id, lane, 0, k3, A3, k2, A2, k1, A1, acc); break;
            case 5: seg_multi<6>(qs, ks, vs, w_id, lane, 0, k3, A3, k2, A2, k1, A1, acc); break;
            case 6: seg_multi<7>(qs, ks, vs, w_id, lane, 0, k3, A3, k2, A2, k1, A1, acc); break;
            case 7: seg_multi<8>(qs, ks, vs, w_id, lane, 0, k3, A3, k2, A2, k1, A1, acc); break;
        }
    } else if (A3) {
        // union = r3; subs = r2, r1
        switch ((w_id & 7) >> 1) {
            case 0: seg_multi<1>(qs, ks, vs, w_id, lane, k3, k2, A2, k1, A1, 0, false, acc); break;
            case 1: seg_multi<2>(qs, ks, vs, w_id, lane, k3, k2, A2, k1, A1, 0, false, acc); break;
            case 2: seg_multi<3>(qs, ks, vs, w_id, lane, k3, k2, A2, k1, A1, 0, false, acc); break;
            case 3: seg_multi<4>(qs, ks, vs, w_id, lane, k3, k2, A2, k1, A1, 0, false, acc); break;
        }
    } else if (A2) {
        // union = r2; sub = r1
        if ((w_id & 3) < 2)
            seg_multi<1>(qs, ks, vs, w_id, lane, k2, k1, A1, 0, false, 0, false, acc);
        else
            seg_multi<2>(qs, ks, vs, w_id, lane, k2, k1, A1, 0, false, 0, false, acc);
    } else if (A1) {
        seg_multi<1>(qs, ks, vs, w_id, lane, k1, 0, false, 0, false, 0, false, acc);
    }

    // write (avg over 4 rates); untouched rows emit zeros
    const int i  = lane >> 3;
    const int kk = lane & 7;
    const int qr = (w_id << 2) + i;
    float* orow = out + base + qr * 64 + kk * 8;
    float4 o0, o1;
    o0.x = acc[0] * 0.25f; o0.y = acc[1] * 0.25f;
    o0.z = acc[2] * 0.25f; o0.w = acc[3] * 0.25f;
    o1.x = acc[4] * 0.25f; o1.y = acc[5] * 0.25f;
    o1.z = acc[6] * 0.25f; o1.w = acc[7] * 0.25f;
    *reinterpret_cast<float4*>(orow)     = o0;
    *reinterpret_cast<float4*>(orow + 4) = o1;
}

extern "C" void kernel_launch(void* const* d_in, const int* in_sizes, int n_in,
                              void* d_out, int out_size)
{
    const float* Q = (const float*)d_in[0];
    const float* K = (const float*)d_in[1];
    const float* V = (const float*)d_in[2];
    float* out = (float*)d_out;

    cudaFuncSetAttribute(dilated_attn_kernel,
                         cudaFuncAttributeMaxDynamicSharedMemorySize, SMEM_BYTES);

    dim3 grid(128, 16, 4);
    dilated_attn_kernel<<<grid, 512, SMEM_BYTES>>>(Q, K, V, out);
}